// round 14
// baseline (speedup 1.0000x reference)
#include <cuda_runtime.h>
#include <cuda_bf16.h>
#include <cstdint>

#define BATCH 8192
#define BT 8            // batches per block
#define NT 256          // threads per block
#define BUFS 18         // h1 slice row stride
#define SES 66          // sE row stride (half-width tile + pad)

// ---- device scratch ----
__device__ __align__(16) float g_Mh[128 * 32];
__device__ __align__(16) float g_Mo[128 * 32];
__device__ __align__(16) float g_G[384 * 96];
__device__ __align__(16) float g_Gb[96];
__device__ __align__(16) float g_G2[96 * 128];
__device__ __align__(16) float g_b2[128];
// B fragments, frag-ordered: [type(3)][ks(16)][ntAbs(16)][lane(32)] = {bhi0,bhi1,blo0,blo1}
__device__ __align__(16) uint4 g_Bfrag[3 * 16 * 16 * 32];

__device__ __forceinline__ uint32_t bf2_bits(__nv_bfloat162 h) {
    return *reinterpret_cast<uint32_t*>(&h);
}
__device__ __forceinline__ uint32_t pack_hi(float a, float b) {   // a -> low half
    return bf2_bits(__floats2bfloat162_rn(a, b));
}
__device__ __forceinline__ void split_pair(float x, float y, uint32_t& hi, uint32_t& lo) {
    __nv_bfloat16 hx = __float2bfloat16_rn(x), hy = __float2bfloat16_rn(y);
    __nv_bfloat16 lx = __float2bfloat16_rn(x - __bfloat162float(hx));
    __nv_bfloat16 ly = __float2bfloat16_rn(y - __bfloat162float(hy));
    __nv_bfloat162 h = __halves2bfloat162(hx, hy);
    __nv_bfloat162 l = __halves2bfloat162(lx, ly);
    hi = bf2_bits(h); lo = bf2_bits(l);
}
__device__ __forceinline__ void mma_bf16(float& d0, float& d1, float& d2, float& d3,
                                         uint32_t a0, uint32_t a1, uint32_t a2, uint32_t a3,
                                         uint32_t b0, uint32_t b1) {
    asm volatile(
        "mma.sync.aligned.m16n8k16.row.col.f32.bf16.bf16.f32 "
        "{%0,%1,%2,%3}, {%4,%5,%6,%7}, {%8,%9}, {%0,%1,%2,%3};"
        : "+f"(d0), "+f"(d1), "+f"(d2), "+f"(d3)
        : "r"(a0), "r"(a1), "r"(a2), "r"(a3), "r"(b0), "r"(b1));
}

// ============================================================
// Kernel P: fold conv weights + build bf16 hi/lo B fragments
// ============================================================
__global__ void prep_kernel(const float* __restrict__ c1_relW,
                            const float* __restrict__ c1_relb,
                            const float* __restrict__ c1_rootW,
                            const float* __restrict__ c2_relW,
                            const float* __restrict__ c2_relb,
                            const float* __restrict__ c2_rootW,
                            const float* __restrict__ whW1,
                            const float* __restrict__ woW1,
                            const float* __restrict__ wrW1) {
    int tid = blockIdx.x * blockDim.x + threadIdx.x;
    int nth = gridDim.x * blockDim.x;

    for (int i = tid; i < 128 * 32; i += nth) {
        g_Mh[i] = c1_rootW[0 * 4096 + i] + c1_rootW[4 * 4096 + i] +
                  c1_rootW[6 * 4096 + i] - c1_relW[6 * 4096 + i];
        g_Mo[i] = c1_rootW[3 * 4096 + i] + c1_rootW[5 * 4096 + i] +
                  c1_rootW[7 * 4096 + i] - c1_relW[7 * 4096 + i];
    }
    for (int i = tid; i < 384 * 96; i += nth) {
        int k = i / 96, c = i % 96;
        int grp = c / 32, cc = c % 32;
        int seg = k / 128, kk = k % 128;
        int idx = kk * 32 + cc;
        float v;
        if (seg == 0) {
            if (grp == 0)      v = c1_relW[0 * 4096 + idx];
            else if (grp == 1) v = c1_relW[3 * 4096 + idx];
            else               v = c1_rootW[1 * 4096 + idx] + c1_rootW[2 * 4096 + idx];
        } else if (seg == 1) {
            if (grp == 0)      v = c1_relW[6 * 4096 + idx];
            else if (grp == 1) v = c1_relW[5 * 4096 + idx];
            else               v = c1_relW[1 * 4096 + idx];
        } else {
            if (grp == 0)      v = c1_relW[4 * 4096 + idx];
            else if (grp == 1) v = c1_relW[7 * 4096 + idx];
            else               v = c1_relW[2 * 4096 + idx];
        }
        g_G[i] = v;
    }
    for (int c = tid; c < 96; c += nth) {
        int grp = c / 32, cc = c % 32;
        float v;
        if (grp == 0)      v = c1_relb[0 * 32 + cc] + c1_relb[4 * 32 + cc] + c1_relb[6 * 32 + cc];
        else if (grp == 1) v = c1_relb[3 * 32 + cc] + c1_relb[5 * 32 + cc] + c1_relb[7 * 32 + cc];
        else               v = c1_relb[1 * 32 + cc] + c1_relb[2 * 32 + cc];
        g_Gb[c] = v;
    }
    for (int i = tid; i < 96 * 128; i += nth) {
        int k = i / 128, c = i % 128;
        float v;
        if (k < 32)      v = c2_relW[1 * 4096 + k * 128 + c];
        else if (k < 64) v = c2_relW[2 * 4096 + (k - 32) * 128 + c];
        else             v = c2_rootW[1 * 4096 + (k - 64) * 128 + c] +
                             c2_rootW[2 * 4096 + (k - 64) * 128 + c];
        g_G2[i] = v;
    }
    for (int c = tid; c < 128; c += nth)
        g_b2[c] = c2_relb[1 * 128 + c] + c2_relb[2 * 128 + c];

    // B fragments (col-major frag for mma.m16n8k16): per (type,ks,ntAbs,lane)
    for (int i = tid; i < 3 * 16 * 16 * 32; i += nth) {
        int lane = i & 31, ntA = (i >> 5) & 15, ks = (i >> 9) & 15, ty = i >> 13;
        const float* W = (ty == 0) ? whW1 : (ty == 1) ? woW1 : wrW1;
        int n = ntA * 8 + (lane >> 2);
        int k0 = ks * 16 + 2 * (lane & 3);
        uint32_t h0, l0, h1, l1;
        split_pair(W[k0 * 128 + n], W[(k0 + 1) * 128 + n], h0, l0);
        split_pair(W[(k0 + 8) * 128 + n], W[(k0 + 9) * 128 + n], h1, l1);
        g_Bfrag[i] = make_uint4(h0, h1, l0, l1);
    }
}

// ============================================================
// Kernel M: tensor-core GEMM + fused epilogue
// ============================================================
// smem (floats): sX 1728 | sBuf 2*128*18=4608 | sE 128*66=8448 | sE2 7680 | sESS 3072
#define MAIN_SMEM_FLOATS 25536   // 102144 bytes -> 2 CTAs/SM

__global__ void __launch_bounds__(NT, 2) main_kernel(
    const float* __restrict__ state,
    const float* __restrict__ wrW0, const float* __restrict__ wrb0,
    const float* __restrict__ wrb1,
    const float* __restrict__ whW0, const float* __restrict__ whb0,
    const float* __restrict__ whb1,
    const float* __restrict__ woW0, const float* __restrict__ wob0,
    const float* __restrict__ wob1,
    const float* __restrict__ vW0, const float* __restrict__ vb0,
    const float* __restrict__ vW1, const float* __restrict__ vb1,
    const float* __restrict__ vW2, const float* __restrict__ vb2,
    float* __restrict__ out) {
    extern __shared__ float sm[];
    float* sXh  = sm;                    // 8 x 20 x 7
    float* sXo  = sXh + BT * 140;        // 8 x 10 x 7
    float* sXr  = sXo + BT * 70;         // 8 x 6
    float* sBuf = sXr + BT * 6;          // 2 x 128 x 18 h1 k-slices
    float* sE   = sBuf + 2 * 128 * BUFS; // 128 x 66 (half-N e tile; later HR + sVEC)
    float* sE2  = sE + 128 * SES;        // 8 x 30 x 32 (later value scratch)
    float* sESS = sE2 + BT * 960;        // 8 x 384 [er|sh|so]
    float* sVEC = sE + 1024;             // alias (after GEMM phase)

    const int tid = threadIdx.x;
    const int b0 = blockIdx.x * BT;
    const int lane = tid & 31, warp = tid >> 5;

    for (int i = tid; i < BT * 140; i += NT) {
        int b = i / 140, r = i % 140, nl = r / 7, f = r % 7;
        sXh[i] = state[(b0 + b) * 390 + nl * 13 + 6 + f];
    }
    for (int i = tid; i < BT * 70; i += NT) {
        int b = i / 70, r = i % 70, nl = r / 7, f = r % 7;
        sXo[i] = state[(b0 + b) * 390 + (20 + nl) * 13 + 6 + f];
    }
    if (tid < BT * 6) {
        int b = tid / 6, f = tid % 6;
        sXr[tid] = state[(b0 + b) * 390 + f];
    }
    for (int i = tid; i < BT * 384; i += NT) sESS[i] = 0.f;
    __syncthreads();

    // producer thread mapping (fixed across passes)
    const int c2 = tid & 7;              // cols {c2, c2+8} of each k-slice
    const int rowgrp = tid >> 3;         // 4 local rows: rowgrp*4..+3

    // consumer (mma) mapping
    const int t4 = lane & 3;
    const int rql = lane >> 2;           // 0..7

    for (int pass = 0; pass < 4; ++pass) {
        const int g = pass >> 1, nh = pass & 1;

        // --- warp strip config ---
        int tI;
        if (g == 0) tI = 0;
        else tI = (warp < 2) ? 0 : (warp < 7) ? 1 : 2;
        const float* b1g = (tI == 0) ? whb1 : (tI == 1) ? wob1 : wrb1;

        // --- producer config: type + x regs (4 rows x 7) ---
        int ptype;
        {
            int absr = g * 128 + rowgrp * 4;
            ptype = (absr < 160) ? 0 : (absr < 240) ? 1 : 2;
        }
        const float* W0g = (ptype == 0) ? whW0 : (ptype == 1) ? woW0 : wrW0;
        const float* b0g = (ptype == 0) ? whb0 : (ptype == 1) ? wob0 : wrb0;
        float xr[4][7];
#pragma unroll
        for (int i = 0; i < 4; ++i) {
            int absr = g * 128 + rowgrp * 4 + i;
            const float* src;
            int nf;
            if (absr < 160)      { int b = absr / 20; src = sXh + b * 140 + (absr % 20) * 7; nf = 7; }
            else if (absr < 240) { int idx = absr - 160; int b = idx / 10; src = sXo + b * 70 + (idx % 10) * 7; nf = 7; }
            else                 { int b = absr - 240; src = (b < 8) ? (sXr + b * 6) : nullptr; nf = 6; }
#pragma unroll
            for (int f = 0; f < 7; ++f)
                xr[i][f] = (src && f < nf) ? src[f] : 0.f;
        }

        float acc[8][4];
#pragma unroll
        for (int n = 0; n < 8; ++n)
#pragma unroll
            for (int j = 0; j < 4; ++j) acc[n][j] = 0.f;

        // --- produce k-slice 0 ---
        {
            float* buf = sBuf;
#pragma unroll
            for (int cc = 0; cc < 2; ++cc) {
                const int c = c2 + cc * 8;
                float w[7];
#pragma unroll
                for (int f = 0; f < 6; ++f) w[f] = W0g[f * 256 + c];
                w[6] = (ptype == 2) ? 0.f : W0g[6 * 256 + c];
                const float bias = b0g[c];
#pragma unroll
                for (int i = 0; i < 4; ++i) {
                    float v = bias;
#pragma unroll
                    for (int f = 0; f < 7; ++f) v += xr[i][f] * w[f];
                    buf[(rowgrp * 4 + i) * BUFS + c] = fmaxf(v, 0.f);
                }
            }
        }
        __syncthreads();

        const int r0 = warp * 16 + rql;
        for (int ks = 0; ks < 16; ++ks) {
            if (ks < 15) {   // produce slice ks+1
                float* buf = sBuf + ((ks + 1) & 1) * (128 * BUFS);
                const int k0 = (ks + 1) * 16;
#pragma unroll
                for (int cc = 0; cc < 2; ++cc) {
                    const int c = c2 + cc * 8;
                    float w[7];
#pragma unroll
                    for (int f = 0; f < 6; ++f) w[f] = W0g[f * 256 + k0 + c];
                    w[6] = (ptype == 2) ? 0.f : W0g[6 * 256 + k0 + c];
                    const float bias = b0g[k0 + c];
#pragma unroll
                    for (int i = 0; i < 4; ++i) {
                        float v = bias;
#pragma unroll
                        for (int f = 0; f < 7; ++f) v += xr[i][f] * w[f];
                        buf[(rowgrp * 4 + i) * BUFS + c] = fmaxf(v, 0.f);
                    }
                }
            }
            // consume slice ks
            {
                const float* buf = sBuf + (ks & 1) * (128 * BUFS);
                float2 p00 = *reinterpret_cast<const float2*>(&buf[r0 * BUFS + 2 * t4]);
                float2 p01 = *reinterpret_cast<const float2*>(&buf[r0 * BUFS + 2 * t4 + 8]);
                float2 p10 = *reinterpret_cast<const float2*>(&buf[(r0 + 8) * BUFS + 2 * t4]);
                float2 p11 = *reinterpret_cast<const float2*>(&buf[(r0 + 8) * BUFS + 2 * t4 + 8]);
                uint32_t ah0, al0, ah1, al1, ah2, al2, ah3, al3;
                split_pair(p00.x, p00.y, ah0, al0);
                split_pair(p10.x, p10.y, ah1, al1);
                split_pair(p01.x, p01.y, ah2, al2);
                split_pair(p11.x, p11.y, ah3, al3);

                const uint4* Bp = g_Bfrag + (((tI * 16 + ks) * 16 + nh * 8) * 32) + lane;
#pragma unroll
                for (int nt = 0; nt < 8; ++nt) {
                    uint4 v = Bp[nt * 32];
                    mma_bf16(acc[nt][0], acc[nt][1], acc[nt][2], acc[nt][3],
                             ah0, ah1, ah2, ah3, v.x, v.y);
                    mma_bf16(acc[nt][0], acc[nt][1], acc[nt][2], acc[nt][3],
                             al0, al1, al2, al3, v.x, v.y);
                    mma_bf16(acc[nt][0], acc[nt][1], acc[nt][2], acc[nt][3],
                             ah0, ah1, ah2, ah3, v.z, v.w);
                }
            }
            __syncthreads();
        }

        // bias + relu -> sE (half-N tile, local cols 0..63)
        {
#pragma unroll
            for (int nt = 0; nt < 8; ++nt) {
                const int c = nt * 8 + 2 * t4;
                const float be = b1g[nh * 64 + c], bo = b1g[nh * 64 + c + 1];
                float2 e0, e1;
                e0.x = fmaxf(acc[nt][0] + be, 0.f);
                e0.y = fmaxf(acc[nt][1] + bo, 0.f);
                e1.x = fmaxf(acc[nt][2] + be, 0.f);
                e1.y = fmaxf(acc[nt][3] + bo, 0.f);
                *reinterpret_cast<float2*>(&sE[r0 * SES + c]) = e0;
                *reinterpret_cast<float2*>(&sE[(r0 + 8) * SES + c]) = e1;
            }
        }
        __syncthreads();

        // per-batch sums -> sESS (+=), segment tables per group
        {
            const int c = tid & 63, slot = tid >> 6;
            const int nsegs = (g == 0) ? 7 : 10;
            for (int i = slot; i < nsegs; i += 4) {
                int s, e, b, off;
                if (g == 0) { s = 20 * i; e = min(128, s + 20); b = i; off = 128; }
                else if (i == 0) { s = 0; e = 12; b = 6; off = 128; }
                else if (i == 1) { s = 12; e = 32; b = 7; off = 128; }
                else { int j = i - 2; s = 32 + 10 * j; e = s + 10; b = j; off = 256; }
                float sum = 0.f;
                for (int r = s; r < e; ++r) sum += sE[r * SES + c];
                sESS[b * 384 + off + nh * 64 + c] += sum;
            }
        }
        // er copy (group 1 only)
        if (g == 1) {
            for (int i = tid; i < 512; i += NT) {
                int b = i >> 6, c = i & 63;
                sESS[b * 384 + nh * 64 + c] = sE[(112 + b) * SES + c];
            }
        }
        // e2 = e @ M (accumulate over halves)
        {
            const int cq = tid & 7, rs = tid >> 3;
            const int nrowmax = (g == 0) ? 128 : 112;
#pragma unroll
            for (int j = 0; j < 4; ++j) {
                const int r = rs + j * 32;
                if (r >= nrowmax) break;
                const int absr = g * 128 + r;
                int b, node;
                const float* Mg;
                if (absr < 160) { b = absr / 20; node = absr % 20; Mg = g_Mh; }
                else { int idx = absr - 160; b = idx / 10; node = 20 + idx % 10; Mg = g_Mo; }
                const float4* M4 = reinterpret_cast<const float4*>(Mg) + cq;
                const float* Er = &sE[r * SES];
                float4 a4 = make_float4(0.f, 0.f, 0.f, 0.f);
#pragma unroll 4
                for (int k = 0; k < 64; ++k) {
                    const float ev = Er[k];
                    const float4 w4 = M4[(nh * 64 + k) * 8];
                    a4.x += ev * w4.x; a4.y += ev * w4.y;
                    a4.z += ev * w4.z; a4.w += ev * w4.w;
                }
                float4* dst = reinterpret_cast<float4*>(&sE2[b * 960 + node * 32]) + cq;
                if (nh == 0) *dst = a4;
                else {
                    float4 p = *dst;
                    p.x += a4.x; p.y += a4.y; p.z += a4.z; p.w += a4.w;
                    *dst = p;
                }
            }
        }
        __syncthreads();
    }

    // ---- conv1 commons + per-node relu sums -> sVEC ----
    {
        const int b = tid >> 5, c0 = tid & 31;
        float a0 = g_Gb[c0], a1 = g_Gb[c0 + 32], a2 = g_Gb[c0 + 64];
        const float* in = &sESS[b * 384];
#pragma unroll 4
        for (int k = 0; k < 384; ++k) {
            const float av = in[k];
            a0 += av * g_G[k * 96 + c0];
            a1 += av * g_G[k * 96 + c0 + 32];
            a2 += av * g_G[k * 96 + c0 + 64];
        }
        float sh2 = 0.f, so2 = 0.f;
        const float* e2b = &sE2[b * 960];
#pragma unroll
        for (int n = 0; n < 20; ++n) sh2 += fmaxf(a0 + e2b[n * 32 + c0], 0.f);
#pragma unroll
        for (int n = 0; n < 10; ++n) so2 += fmaxf(a1 + e2b[(20 + n) * 32 + c0], 0.f);
        sVEC[b * 96 + c0]      = sh2;
        sVEC[b * 96 + 32 + c0] = so2;
        sVEC[b * 96 + 64 + c0] = fmaxf(a2, 0.f);
    }
    __syncthreads();

    // ---- hr = relu([sh2|so2|r1] @ G2 + b2) -> sE[0..1023] ----
    {
        const int b = tid >> 5, cg = tid & 31;
        float a[4];
#pragma unroll
        for (int j = 0; j < 4; ++j) a[j] = g_b2[cg + 32 * j];
        const float* in = &sVEC[b * 96];
#pragma unroll 4
        for (int k = 0; k < 96; ++k) {
            const float av = in[k];
#pragma unroll
            for (int j = 0; j < 4; ++j) a[j] += av * g_G2[k * 128 + cg + 32 * j];
        }
#pragma unroll
        for (int j = 0; j < 4; ++j)
            sE[b * 128 + cg + 32 * j] = fmaxf(a[j], 0.f);
    }
    __syncthreads();

    // ---- value MLP ----
    {
        const int col = tid;
        float a[8];
        const float bias = vb0[col];
#pragma unroll
        for (int i = 0; i < 8; ++i) a[i] = bias;
#pragma unroll 4
        for (int k = 0; k < 128; ++k) {
            const float w = vW0[k * 256 + col];
#pragma unroll
            for (int i = 0; i < 8; ++i) a[i] += sE[i * 128 + k] * w;
        }
#pragma unroll
        for (int i = 0; i < 8; ++i)
            sE2[i * 256 + col] = fmaxf(a[i], 0.f);
    }
    __syncthreads();
    {
        const int col = tid & 127, gq = tid >> 7;
        float a[4];
        const float bias = vb1[col];
#pragma unroll
        for (int i = 0; i < 4; ++i) a[i] = bias;
#pragma unroll 4
        for (int k = 0; k < 256; ++k) {
            const float w = vW1[k * 128 + col];
#pragma unroll
            for (int i = 0; i < 4; ++i) a[i] += sE2[(gq * 4 + i) * 256 + k] * w;
        }
#pragma unroll
        for (int i = 0; i < 4; ++i)
            sE2[2048 + (gq * 4 + i) * 128 + col] = fmaxf(a[i], 0.f);
    }
    __syncthreads();
    {
        const int b = warp, l = lane;
        float s = 0.f;
#pragma unroll
        for (int k = l; k < 128; k += 32) s += sE2[2048 + b * 128 + k] * vW2[k];
#pragma unroll
        for (int off = 16; off > 0; off >>= 1)
            s += __shfl_down_sync(0xffffffffu, s, off);
        if (l == 0) out[b0 + b] = s + vb2[0];
    }
}

// ============================================================
extern "C" void kernel_launch(void* const* d_in, const int* in_sizes, int n_in,
                              void* d_out, int out_size) {
    const float* state   = (const float*)d_in[0];
    const float* wrW0    = (const float*)d_in[2];
    const float* wrb0    = (const float*)d_in[3];
    const float* wrW1    = (const float*)d_in[4];
    const float* wrb1    = (const float*)d_in[5];
    const float* whW0    = (const float*)d_in[6];
    const float* whb0    = (const float*)d_in[7];
    const float* whW1    = (const float*)d_in[8];
    const float* whb1    = (const float*)d_in[9];
    const float* woW0    = (const float*)d_in[10];
    const float* wob0    = (const float*)d_in[11];
    const float* woW1    = (const float*)d_in[12];
    const float* wob1    = (const float*)d_in[13];
    const float* c1_relW = (const float*)d_in[14];
    const float* c1_relb = (const float*)d_in[15];
    const float* c1_rootW= (const float*)d_in[16];
    const float* c2_relW = (const float*)d_in[17];
    const float* c2_relb = (const float*)d_in[18];
    const float* c2_rootW= (const float*)d_in[19];
    const float* vW0     = (const float*)d_in[20];
    const float* vb0     = (const float*)d_in[21];
    const float* vW1     = (const float*)d_in[22];
    const float* vb1     = (const float*)d_in[23];
    const float* vW2     = (const float*)d_in[24];
    const float* vb2     = (const float*)d_in[25];
    float* out = (float*)d_out;

    cudaFuncSetAttribute(main_kernel, cudaFuncAttributeMaxDynamicSharedMemorySize,
                         MAIN_SMEM_FLOATS * 4);

    prep_kernel<<<96, 256>>>(c1_relW, c1_relb, c1_rootW, c2_relW, c2_relb, c2_rootW,
                             whW1, woW1, wrW1);

    main_kernel<<<BATCH / BT, NT, MAIN_SMEM_FLOATS * 4>>>(
        state, wrW0, wrb0, wrb1, whW0, whb0, whb1,
        woW0, wob0, wob1,
        vW0, vb0, vW1, vb1, vW2, vb2, out);
}

// round 16
// speedup vs baseline: 1.0003x; 1.0003x over previous
#include <cuda_runtime.h>
#include <cuda_bf16.h>
#include <cstdint>

#define BATCH 8192
#define BT 8            // batches per block
#define NT 256          // threads per block
#define BUFS 18         // h1 slice row stride
#define SES 66          // sE row stride (half-width tile + pad)

// ---- device scratch ----
__device__ __align__(16) float g_Mh[128 * 32];
__device__ __align__(16) float g_Mo[128 * 32];
__device__ __align__(16) float g_G[384 * 96];
__device__ __align__(16) float g_Gb[96];
__device__ __align__(16) float g_G2[96 * 128];
__device__ __align__(16) float g_b2[128];
// B fragments, frag-ordered: [type(3)][ks(16)][ntAbs(16)][lane(32)] = {bhi0,bhi1,blo0,blo1}
__device__ __align__(16) uint4 g_Bfrag[3 * 16 * 16 * 32];

__device__ __forceinline__ uint32_t bf2_bits(__nv_bfloat162 h) {
    return *reinterpret_cast<uint32_t*>(&h);
}
__device__ __forceinline__ uint32_t pack_hi(float a, float b) {   // a -> low half
    return bf2_bits(__floats2bfloat162_rn(a, b));
}
__device__ __forceinline__ void split_pair(float x, float y, uint32_t& hi, uint32_t& lo) {
    __nv_bfloat16 hx = __float2bfloat16_rn(x), hy = __float2bfloat16_rn(y);
    __nv_bfloat16 lx = __float2bfloat16_rn(x - __bfloat162float(hx));
    __nv_bfloat16 ly = __float2bfloat16_rn(y - __bfloat162float(hy));
    __nv_bfloat162 h = __halves2bfloat162(hx, hy);
    __nv_bfloat162 l = __halves2bfloat162(lx, ly);
    hi = bf2_bits(h); lo = bf2_bits(l);
}
__device__ __forceinline__ void mma_bf16(float& d0, float& d1, float& d2, float& d3,
                                         uint32_t a0, uint32_t a1, uint32_t a2, uint32_t a3,
                                         uint32_t b0, uint32_t b1) {
    asm volatile(
        "mma.sync.aligned.m16n8k16.row.col.f32.bf16.bf16.f32 "
        "{%0,%1,%2,%3}, {%4,%5,%6,%7}, {%8,%9}, {%0,%1,%2,%3};"
        : "+f"(d0), "+f"(d1), "+f"(d2), "+f"(d3)
        : "r"(a0), "r"(a1), "r"(a2), "r"(a3), "r"(b0), "r"(b1));
}

// ============================================================
// Kernel P: fold conv weights + build bf16 hi/lo B fragments
// ============================================================
__global__ void prep_kernel(const float* __restrict__ c1_relW,
                            const float* __restrict__ c1_relb,
                            const float* __restrict__ c1_rootW,
                            const float* __restrict__ c2_relW,
                            const float* __restrict__ c2_relb,
                            const float* __restrict__ c2_rootW,
                            const float* __restrict__ whW1,
                            const float* __restrict__ woW1,
                            const float* __restrict__ wrW1) {
    int tid = blockIdx.x * blockDim.x + threadIdx.x;
    int nth = gridDim.x * blockDim.x;

    for (int i = tid; i < 128 * 32; i += nth) {
        g_Mh[i] = c1_rootW[0 * 4096 + i] + c1_rootW[4 * 4096 + i] +
                  c1_rootW[6 * 4096 + i] - c1_relW[6 * 4096 + i];
        g_Mo[i] = c1_rootW[3 * 4096 + i] + c1_rootW[5 * 4096 + i] +
                  c1_rootW[7 * 4096 + i] - c1_relW[7 * 4096 + i];
    }
    for (int i = tid; i < 384 * 96; i += nth) {
        int k = i / 96, c = i % 96;
        int grp = c / 32, cc = c % 32;
        int seg = k / 128, kk = k % 128;
        int idx = kk * 32 + cc;
        float v;
        if (seg == 0) {
            if (grp == 0)      v = c1_relW[0 * 4096 + idx];
            else if (grp == 1) v = c1_relW[3 * 4096 + idx];
            else               v = c1_rootW[1 * 4096 + idx] + c1_rootW[2 * 4096 + idx];
        } else if (seg == 1) {
            if (grp == 0)      v = c1_relW[6 * 4096 + idx];
            else if (grp == 1) v = c1_relW[5 * 4096 + idx];
            else               v = c1_relW[1 * 4096 + idx];
        } else {
            if (grp == 0)      v = c1_relW[4 * 4096 + idx];
            else if (grp == 1) v = c1_relW[7 * 4096 + idx];
            else               v = c1_relW[2 * 4096 + idx];
        }
        g_G[i] = v;
    }
    for (int c = tid; c < 96; c += nth) {
        int grp = c / 32, cc = c % 32;
        float v;
        if (grp == 0)      v = c1_relb[0 * 32 + cc] + c1_relb[4 * 32 + cc] + c1_relb[6 * 32 + cc];
        else if (grp == 1) v = c1_relb[3 * 32 + cc] + c1_relb[5 * 32 + cc] + c1_relb[7 * 32 + cc];
        else               v = c1_relb[1 * 32 + cc] + c1_relb[2 * 32 + cc];
        g_Gb[c] = v;
    }
    for (int i = tid; i < 96 * 128; i += nth) {
        int k = i / 128, c = i % 128;
        float v;
        if (k < 32)      v = c2_relW[1 * 4096 + k * 128 + c];
        else if (k < 64) v = c2_relW[2 * 4096 + (k - 32) * 128 + c];
        else             v = c2_rootW[1 * 4096 + (k - 64) * 128 + c] +
                             c2_rootW[2 * 4096 + (k - 64) * 128 + c];
        g_G2[i] = v;
    }
    for (int c = tid; c < 128; c += nth)
        g_b2[c] = c2_relb[1 * 128 + c] + c2_relb[2 * 128 + c];

    // B fragments (col-major frag for mma.m16n8k16): per (type,ks,ntAbs,lane)
    for (int i = tid; i < 3 * 16 * 16 * 32; i += nth) {
        int lane = i & 31, ntA = (i >> 5) & 15, ks = (i >> 9) & 15, ty = i >> 13;
        const float* W = (ty == 0) ? whW1 : (ty == 1) ? woW1 : wrW1;
        int n = ntA * 8 + (lane >> 2);
        int k0 = ks * 16 + 2 * (lane & 3);
        uint32_t h0, l0, h1, l1;
        split_pair(W[k0 * 128 + n], W[(k0 + 1) * 128 + n], h0, l0);
        split_pair(W[(k0 + 8) * 128 + n], W[(k0 + 9) * 128 + n], h1, l1);
        g_Bfrag[i] = make_uint4(h0, h1, l0, l1);
    }
}

// ============================================================
// Kernel M: tensor-core GEMM + fused epilogue
// ============================================================
// smem (floats): sX 1728 | sBuf 2*128*18=4608 | sE 128*66=8448 | sE2 7680 | sESS 3072
#define MAIN_SMEM_FLOATS 25536   // 102144 bytes -> 2 CTAs/SM

__global__ void __launch_bounds__(NT, 2) main_kernel(
    const float* __restrict__ state,
    const float* __restrict__ wrW0, const float* __restrict__ wrb0,
    const float* __restrict__ wrb1,
    const float* __restrict__ whW0, const float* __restrict__ whb0,
    const float* __restrict__ whb1,
    const float* __restrict__ woW0, const float* __restrict__ wob0,
    const float* __restrict__ wob1,
    const float* __restrict__ vW0, const float* __restrict__ vb0,
    const float* __restrict__ vW1, const float* __restrict__ vb1,
    const float* __restrict__ vW2, const float* __restrict__ vb2,
    float* __restrict__ out) {
    extern __shared__ float sm[];
    float* sXh  = sm;                    // 8 x 20 x 7
    float* sXo  = sXh + BT * 140;        // 8 x 10 x 7
    float* sXr  = sXo + BT * 70;         // 8 x 6
    float* sBuf = sXr + BT * 6;          // 2 x 128 x 18 h1 k-slices
    float* sE   = sBuf + 2 * 128 * BUFS; // 128 x 66 (half-N e tile; later HR + sVEC)
    float* sE2  = sE + 128 * SES;        // 8 x 30 x 32 (later value scratch)
    float* sESS = sE2 + BT * 960;        // 8 x 384 [er|sh|so]
    float* sVEC = sE + 1024;             // alias (after GEMM phase)

    const int tid = threadIdx.x;
    const int b0 = blockIdx.x * BT;
    const int lane = tid & 31, warp = tid >> 5;

    for (int i = tid; i < BT * 140; i += NT) {
        int b = i / 140, r = i % 140, nl = r / 7, f = r % 7;
        sXh[i] = state[(b0 + b) * 390 + nl * 13 + 6 + f];
    }
    for (int i = tid; i < BT * 70; i += NT) {
        int b = i / 70, r = i % 70, nl = r / 7, f = r % 7;
        sXo[i] = state[(b0 + b) * 390 + (20 + nl) * 13 + 6 + f];
    }
    if (tid < BT * 6) {
        int b = tid / 6, f = tid % 6;
        sXr[tid] = state[(b0 + b) * 390 + f];
    }
    for (int i = tid; i < BT * 384; i += NT) sESS[i] = 0.f;
    __syncthreads();

    // producer thread mapping (fixed across passes)
    const int c2 = tid & 7;              // cols {c2, c2+8} of each k-slice
    const int rowgrp = tid >> 3;         // 4 local rows: rowgrp*4..+3

    // consumer (mma) mapping
    const int t4 = lane & 3;
    const int rql = lane >> 2;           // 0..7

    for (int pass = 0; pass < 4; ++pass) {
        const int g = pass >> 1, nh = pass & 1;

        // --- warp strip config ---
        int tI;
        if (g == 0) tI = 0;
        else tI = (warp < 2) ? 0 : (warp < 7) ? 1 : 2;
        const float* b1g = (tI == 0) ? whb1 : (tI == 1) ? wob1 : wrb1;

        // --- producer config: type + x regs (4 rows x 7) ---
        int ptype;
        {
            int absr = g * 128 + rowgrp * 4;
            ptype = (absr < 160) ? 0 : (absr < 240) ? 1 : 2;
        }
        const float* W0g = (ptype == 0) ? whW0 : (ptype == 1) ? woW0 : wrW0;
        const float* b0g = (ptype == 0) ? whb0 : (ptype == 1) ? wob0 : wrb0;
        float xr[4][7];
#pragma unroll
        for (int i = 0; i < 4; ++i) {
            int absr = g * 128 + rowgrp * 4 + i;
            const float* src;
            int nf;
            if (absr < 160)      { int b = absr / 20; src = sXh + b * 140 + (absr % 20) * 7; nf = 7; }
            else if (absr < 240) { int idx = absr - 160; int b = idx / 10; src = sXo + b * 70 + (idx % 10) * 7; nf = 7; }
            else                 { int b = absr - 240; src = (b < 8) ? (sXr + b * 6) : nullptr; nf = 6; }
#pragma unroll
            for (int f = 0; f < 7; ++f)
                xr[i][f] = (src && f < nf) ? src[f] : 0.f;
        }

        float acc[8][4];
#pragma unroll
        for (int n = 0; n < 8; ++n)
#pragma unroll
            for (int j = 0; j < 4; ++j) acc[n][j] = 0.f;

        // --- produce k-slice 0 ---
        {
            float* buf = sBuf;
#pragma unroll
            for (int cc = 0; cc < 2; ++cc) {
                const int c = c2 + cc * 8;
                float w[7];
#pragma unroll
                for (int f = 0; f < 6; ++f) w[f] = W0g[f * 256 + c];
                w[6] = (ptype == 2) ? 0.f : W0g[6 * 256 + c];
                const float bias = b0g[c];
#pragma unroll
                for (int i = 0; i < 4; ++i) {
                    float v = bias;
#pragma unroll
                    for (int f = 0; f < 7; ++f) v += xr[i][f] * w[f];
                    buf[(rowgrp * 4 + i) * BUFS + c] = fmaxf(v, 0.f);
                }
            }
        }
        __syncthreads();

        const int r0 = warp * 16 + rql;
        for (int ks = 0; ks < 16; ++ks) {
            if (ks < 15) {   // produce slice ks+1
                float* buf = sBuf + ((ks + 1) & 1) * (128 * BUFS);
                const int k0 = (ks + 1) * 16;
#pragma unroll
                for (int cc = 0; cc < 2; ++cc) {
                    const int c = c2 + cc * 8;
                    float w[7];
#pragma unroll
                    for (int f = 0; f < 6; ++f) w[f] = W0g[f * 256 + k0 + c];
                    w[6] = (ptype == 2) ? 0.f : W0g[6 * 256 + k0 + c];
                    const float bias = b0g[k0 + c];
#pragma unroll
                    for (int i = 0; i < 4; ++i) {
                        float v = bias;
#pragma unroll
                        for (int f = 0; f < 7; ++f) v += xr[i][f] * w[f];
                        buf[(rowgrp * 4 + i) * BUFS + c] = fmaxf(v, 0.f);
                    }
                }
            }
            // consume slice ks
            {
                const float* buf = sBuf + (ks & 1) * (128 * BUFS);
                float2 p00 = *reinterpret_cast<const float2*>(&buf[r0 * BUFS + 2 * t4]);
                float2 p01 = *reinterpret_cast<const float2*>(&buf[r0 * BUFS + 2 * t4 + 8]);
                float2 p10 = *reinterpret_cast<const float2*>(&buf[(r0 + 8) * BUFS + 2 * t4]);
                float2 p11 = *reinterpret_cast<const float2*>(&buf[(r0 + 8) * BUFS + 2 * t4 + 8]);
                uint32_t ah0, al0, ah1, al1, ah2, al2, ah3, al3;
                split_pair(p00.x, p00.y, ah0, al0);
                split_pair(p10.x, p10.y, ah1, al1);
                split_pair(p01.x, p01.y, ah2, al2);
                split_pair(p11.x, p11.y, ah3, al3);

                const uint4* Bp = g_Bfrag + (((tI * 16 + ks) * 16 + nh * 8) * 32) + lane;
#pragma unroll
                for (int nt = 0; nt < 8; ++nt) {
                    uint4 v = Bp[nt * 32];
                    mma_bf16(acc[nt][0], acc[nt][1], acc[nt][2], acc[nt][3],
                             ah0, ah1, ah2, ah3, v.x, v.y);
                    mma_bf16(acc[nt][0], acc[nt][1], acc[nt][2], acc[nt][3],
                             al0, al1, al2, al3, v.x, v.y);
                    mma_bf16(acc[nt][0], acc[nt][1], acc[nt][2], acc[nt][3],
                             ah0, ah1, ah2, ah3, v.z, v.w);
                }
            }
            __syncthreads();
        }

        // bias + relu -> sE (half-N tile, local cols 0..63)
        {
#pragma unroll
            for (int nt = 0; nt < 8; ++nt) {
                const int c = nt * 8 + 2 * t4;
                const float be = b1g[nh * 64 + c], bo = b1g[nh * 64 + c + 1];
                float2 e0, e1;
                e0.x = fmaxf(acc[nt][0] + be, 0.f);
                e0.y = fmaxf(acc[nt][1] + bo, 0.f);
                e1.x = fmaxf(acc[nt][2] + be, 0.f);
                e1.y = fmaxf(acc[nt][3] + bo, 0.f);
                *reinterpret_cast<float2*>(&sE[r0 * SES + c]) = e0;
                *reinterpret_cast<float2*>(&sE[(r0 + 8) * SES + c]) = e1;
            }
        }
        __syncthreads();

        // per-batch sums -> sESS (+=), segment tables per group
        {
            const int c = tid & 63, slot = tid >> 6;
            const int nsegs = (g == 0) ? 7 : 10;
            for (int i = slot; i < nsegs; i += 4) {
                int s, e, b, off;
                if (g == 0) { s = 20 * i; e = min(128, s + 20); b = i; off = 128; }
                else if (i == 0) { s = 0; e = 12; b = 6; off = 128; }
                else if (i == 1) { s = 12; e = 32; b = 7; off = 128; }
                else { int j = i - 2; s = 32 + 10 * j; e = s + 10; b = j; off = 256; }
                float sum = 0.f;
                for (int r = s; r < e; ++r) sum += sE[r * SES + c];
                sESS[b * 384 + off + nh * 64 + c] += sum;
            }
        }
        // er copy (group 1 only)
        if (g == 1) {
            for (int i = tid; i < 512; i += NT) {
                int b = i >> 6, c = i & 63;
                sESS[b * 384 + nh * 64 + c] = sE[(112 + b) * SES + c];
            }
        }
        // e2 = e @ M (accumulate over halves)
        {
            const int cq = tid & 7, rs = tid >> 3;
            const int nrowmax = (g == 0) ? 128 : 112;
#pragma unroll
            for (int j = 0; j < 4; ++j) {
                const int r = rs + j * 32;
                if (r >= nrowmax) break;
                const int absr = g * 128 + r;
                int b, node;
                const float* Mg;
                if (absr < 160) { b = absr / 20; node = absr % 20; Mg = g_Mh; }
                else { int idx = absr - 160; b = idx / 10; node = 20 + idx % 10; Mg = g_Mo; }
                const float4* M4 = reinterpret_cast<const float4*>(Mg) + cq;
                const float* Er = &sE[r * SES];
                float4 a4 = make_float4(0.f, 0.f, 0.f, 0.f);
#pragma unroll 4
                for (int k = 0; k < 64; ++k) {
                    const float ev = Er[k];
                    const float4 w4 = M4[(nh * 64 + k) * 8];
                    a4.x += ev * w4.x; a4.y += ev * w4.y;
                    a4.z += ev * w4.z; a4.w += ev * w4.w;
                }
                float4* dst = reinterpret_cast<float4*>(&sE2[b * 960 + node * 32]) + cq;
                if (nh == 0) *dst = a4;
                else {
                    float4 p = *dst;
                    p.x += a4.x; p.y += a4.y; p.z += a4.z; p.w += a4.w;
                    *dst = p;
                }
            }
        }
        __syncthreads();
    }

    // ---- conv1 commons + per-node relu sums -> sVEC ----
    {
        const int b = tid >> 5, c0 = tid & 31;
        float a0 = g_Gb[c0], a1 = g_Gb[c0 + 32], a2 = g_Gb[c0 + 64];
        const float* in = &sESS[b * 384];
#pragma unroll 4
        for (int k = 0; k < 384; ++k) {
            const float av = in[k];
            a0 += av * g_G[k * 96 + c0];
            a1 += av * g_G[k * 96 + c0 + 32];
            a2 += av * g_G[k * 96 + c0 + 64];
        }
        float sh2 = 0.f, so2 = 0.f;
        const float* e2b = &sE2[b * 960];
#pragma unroll
        for (int n = 0; n < 20; ++n) sh2 += fmaxf(a0 + e2b[n * 32 + c0], 0.f);
#pragma unroll
        for (int n = 0; n < 10; ++n) so2 += fmaxf(a1 + e2b[(20 + n) * 32 + c0], 0.f);
        sVEC[b * 96 + c0]      = sh2;
        sVEC[b * 96 + 32 + c0] = so2;
        sVEC[b * 96 + 64 + c0] = fmaxf(a2, 0.f);
    }
    __syncthreads();

    // ---- hr = relu([sh2|so2|r1] @ G2 + b2) -> sE[0..1023] ----
    {
        const int b = tid >> 5, cg = tid & 31;
        float a[4];
#pragma unroll
        for (int j = 0; j < 4; ++j) a[j] = g_b2[cg + 32 * j];
        const float* in = &sVEC[b * 96];
#pragma unroll 4
        for (int k = 0; k < 96; ++k) {
            const float av = in[k];
#pragma unroll
            for (int j = 0; j < 4; ++j) a[j] += av * g_G2[k * 128 + cg + 32 * j];
        }
#pragma unroll
        for (int j = 0; j < 4; ++j)
            sE[b * 128 + cg + 32 * j] = fmaxf(a[j], 0.f);
    }
    __syncthreads();

    // ---- value MLP ----
    {
        const int col = tid;
        float a[8];
        const float bias = vb0[col];
#pragma unroll
        for (int i = 0; i < 8; ++i) a[i] = bias;
#pragma unroll 4
        for (int k = 0; k < 128; ++k) {
            const float w = vW0[k * 256 + col];
#pragma unroll
            for (int i = 0; i < 8; ++i) a[i] += sE[i * 128 + k] * w;
        }
#pragma unroll
        for (int i = 0; i < 8; ++i)
            sE2[i * 256 + col] = fmaxf(a[i], 0.f);
    }
    __syncthreads();
    {
        const int col = tid & 127, gq = tid >> 7;
        float a[4];
        const float bias = vb1[col];
#pragma unroll
        for (int i = 0; i < 4; ++i) a[i] = bias;
#pragma unroll 4
        for (int k = 0; k < 256; ++k) {
            const float w = vW1[k * 128 + col];
#pragma unroll
            for (int i = 0; i < 4; ++i) a[i] += sE2[(gq * 4 + i) * 256 + k] * w;
        }
#pragma unroll
        for (int i = 0; i < 4; ++i)
            sE2[2048 + (gq * 4 + i) * 128 + col] = fmaxf(a[i], 0.f);
    }
    __syncthreads();
    {
        const int b = warp, l = lane;
        float s = 0.f;
#pragma unroll
        for (int k = l; k < 128; k += 32) s += sE2[2048 + b * 128 + k] * vW2[k];
#pragma unroll
        for (int off = 16; off > 0; off >>= 1)
            s += __shfl_down_sync(0xffffffffu, s, off);
        if (l == 0) out[b0 + b] = s + vb2[0];
    }
}

// ============================================================
extern "C" void kernel_launch(void* const* d_in, const int* in_sizes, int n_in,
                              void* d_out, int out_size) {
    const float* state   = (const float*)d_in[0];
    const float* wrW0    = (const float*)d_in[2];
    const float* wrb0    = (const float*)d_in[3];
    const float* wrW1    = (const float*)d_in[4];
    const float* wrb1    = (const float*)d_in[5];
    const float* whW0    = (const float*)d_in[6];
    const float* whb0    = (const float*)d_in[7];
    const float* whW1    = (const float*)d_in[8];
    const float* whb1    = (const float*)d_in[9];
    const float* woW0    = (const float*)d_in[10];
    const float* wob0    = (const float*)d_in[11];
    const float* woW1    = (const float*)d_in[12];
    const float* wob1    = (const float*)d_in[13];
    const float* c1_relW = (const float*)d_in[14];
    const float* c1_relb = (const float*)d_in[15];
    const float* c1_rootW= (const float*)d_in[16];
    const float* c2_relW = (const float*)d_in[17];
    const float* c2_relb = (const float*)d_in[18];
    const float* c2_rootW= (const float*)d_in[19];
    const float* vW0     = (const float*)d_in[20];
    const float* vb0     = (const float*)d_in[21];
    const float* vW1     = (const float*)d_in[22];
    const float* vb1     = (const float*)d_in[23];
    const float* vW2     = (const float*)d_in[24];
    const float* vb2     = (const float*)d_in[25];
    float* out = (float*)d_out;

    cudaFuncSetAttribute(main_kernel, cudaFuncAttributeMaxDynamicSharedMemorySize,
                         MAIN_SMEM_FLOATS * 4);

    prep_kernel<<<96, 256>>>(c1_relW, c1_relb, c1_rootW, c2_relW, c2_relb, c2_rootW,
                             whW1, woW1, wrW1);

    main_kernel<<<BATCH / BT, NT, MAIN_SMEM_FLOATS * 4>>>(
        state, wrW0, wrb0, wrb1, whW0, whb0, whb1,
        woW0, wob0, wob1,
        vW0, vb0, vW1, vb1, vW2, vb2, out);
}

// round 17
// speedup vs baseline: 1.0031x; 1.0027x over previous
#include <cuda_runtime.h>
#include <cuda_bf16.h>
#include <cstdint>

#define BATCH 8192
#define BT 8            // batches per block
#define NT 256          // threads per block
#define BUFS 18         // h1 slice row stride
#define SES 66          // sE row stride (half-width tile + pad)

// ---- device scratch ----
__device__ __align__(16) float g_Mh[128 * 32];
__device__ __align__(16) float g_Mo[128 * 32];
__device__ __align__(16) float g_G[384 * 96];
__device__ __align__(16) float g_Gb[96];
__device__ __align__(16) float g_G2[96 * 128];
__device__ __align__(16) float g_b2[128];
// B fragments, frag-ordered: [type(3)][ks(16)][ntAbs(16)][lane(32)] = {bhi0,bhi1,blo0,blo1}
__device__ __align__(16) uint4 g_Bfrag[3 * 16 * 16 * 32];

__device__ __forceinline__ uint32_t bf2_bits(__nv_bfloat162 h) {
    return *reinterpret_cast<uint32_t*>(&h);
}
__device__ __forceinline__ uint32_t pack_hi(float a, float b) {   // a -> low half
    return bf2_bits(__floats2bfloat162_rn(a, b));
}
__device__ __forceinline__ void split_pair(float x, float y, uint32_t& hi, uint32_t& lo) {
    __nv_bfloat16 hx = __float2bfloat16_rn(x), hy = __float2bfloat16_rn(y);
    __nv_bfloat16 lx = __float2bfloat16_rn(x - __bfloat162float(hx));
    __nv_bfloat16 ly = __float2bfloat16_rn(y - __bfloat162float(hy));
    __nv_bfloat162 h = __halves2bfloat162(hx, hy);
    __nv_bfloat162 l = __halves2bfloat162(lx, ly);
    hi = bf2_bits(h); lo = bf2_bits(l);
}
__device__ __forceinline__ void mma_bf16(float& d0, float& d1, float& d2, float& d3,
                                         uint32_t a0, uint32_t a1, uint32_t a2, uint32_t a3,
                                         uint32_t b0, uint32_t b1) {
    asm volatile(
        "mma.sync.aligned.m16n8k16.row.col.f32.bf16.bf16.f32 "
        "{%0,%1,%2,%3}, {%4,%5,%6,%7}, {%8,%9}, {%0,%1,%2,%3};"
        : "+f"(d0), "+f"(d1), "+f"(d2), "+f"(d3)
        : "r"(a0), "r"(a1), "r"(a2), "r"(a3), "r"(b0), "r"(b1));
}

// ============================================================
// Kernel P: fold conv weights + build bf16 hi/lo B fragments
// ============================================================
__global__ void prep_kernel(const float* __restrict__ c1_relW,
                            const float* __restrict__ c1_relb,
                            const float* __restrict__ c1_rootW,
                            const float* __restrict__ c2_relW,
                            const float* __restrict__ c2_relb,
                            const float* __restrict__ c2_rootW,
                            const float* __restrict__ whW1,
                            const float* __restrict__ woW1,
                            const float* __restrict__ wrW1) {
    int tid = blockIdx.x * blockDim.x + threadIdx.x;
    int nth = gridDim.x * blockDim.x;

    for (int i = tid; i < 128 * 32; i += nth) {
        g_Mh[i] = c1_rootW[0 * 4096 + i] + c1_rootW[4 * 4096 + i] +
                  c1_rootW[6 * 4096 + i] - c1_relW[6 * 4096 + i];
        g_Mo[i] = c1_rootW[3 * 4096 + i] + c1_rootW[5 * 4096 + i] +
                  c1_rootW[7 * 4096 + i] - c1_relW[7 * 4096 + i];
    }
    for (int i = tid; i < 384 * 96; i += nth) {
        int k = i / 96, c = i % 96;
        int grp = c / 32, cc = c % 32;
        int seg = k / 128, kk = k % 128;
        int idx = kk * 32 + cc;
        float v;
        if (seg == 0) {
            if (grp == 0)      v = c1_relW[0 * 4096 + idx];
            else if (grp == 1) v = c1_relW[3 * 4096 + idx];
            else               v = c1_rootW[1 * 4096 + idx] + c1_rootW[2 * 4096 + idx];
        } else if (seg == 1) {
            if (grp == 0)      v = c1_relW[6 * 4096 + idx];
            else if (grp == 1) v = c1_relW[5 * 4096 + idx];
            else               v = c1_relW[1 * 4096 + idx];
        } else {
            if (grp == 0)      v = c1_relW[4 * 4096 + idx];
            else if (grp == 1) v = c1_relW[7 * 4096 + idx];
            else               v = c1_relW[2 * 4096 + idx];
        }
        g_G[i] = v;
    }
    for (int c = tid; c < 96; c += nth) {
        int grp = c / 32, cc = c % 32;
        float v;
        if (grp == 0)      v = c1_relb[0 * 32 + cc] + c1_relb[4 * 32 + cc] + c1_relb[6 * 32 + cc];
        else if (grp == 1) v = c1_relb[3 * 32 + cc] + c1_relb[5 * 32 + cc] + c1_relb[7 * 32 + cc];
        else               v = c1_relb[1 * 32 + cc] + c1_relb[2 * 32 + cc];
        g_Gb[c] = v;
    }
    for (int i = tid; i < 96 * 128; i += nth) {
        int k = i / 128, c = i % 128;
        float v;
        if (k < 32)      v = c2_relW[1 * 4096 + k * 128 + c];
        else if (k < 64) v = c2_relW[2 * 4096 + (k - 32) * 128 + c];
        else             v = c2_rootW[1 * 4096 + (k - 64) * 128 + c] +
                             c2_rootW[2 * 4096 + (k - 64) * 128 + c];
        g_G2[i] = v;
    }
    for (int c = tid; c < 128; c += nth)
        g_b2[c] = c2_relb[1 * 128 + c] + c2_relb[2 * 128 + c];

    // B fragments (col-major frag for mma.m16n8k16): per (type,ks,ntAbs,lane)
    for (int i = tid; i < 3 * 16 * 16 * 32; i += nth) {
        int lane = i & 31, ntA = (i >> 5) & 15, ks = (i >> 9) & 15, ty = i >> 13;
        const float* W = (ty == 0) ? whW1 : (ty == 1) ? woW1 : wrW1;
        int n = ntA * 8 + (lane >> 2);
        int k0 = ks * 16 + 2 * (lane & 3);
        uint32_t h0, l0, h1, l1;
        split_pair(W[k0 * 128 + n], W[(k0 + 1) * 128 + n], h0, l0);
        split_pair(W[(k0 + 8) * 128 + n], W[(k0 + 9) * 128 + n], h1, l1);
        g_Bfrag[i] = make_uint4(h0, h1, l0, l1);
    }
}

// ============================================================
// Kernel M: tensor-core GEMM + fused epilogue
// ============================================================
// smem (floats): sX 1728 | sBuf 2*128*18=4608 | sE 128*66=8448 | sE2 7680 | sESS 3072
#define MAIN_SMEM_FLOATS 25536   // 102144 bytes -> 2 CTAs/SM

__global__ void __launch_bounds__(NT, 2) main_kernel(
    const float* __restrict__ state,
    const float* __restrict__ wrW0, const float* __restrict__ wrb0,
    const float* __restrict__ wrb1,
    const float* __restrict__ whW0, const float* __restrict__ whb0,
    const float* __restrict__ whb1,
    const float* __restrict__ woW0, const float* __restrict__ wob0,
    const float* __restrict__ wob1,
    const float* __restrict__ vW0, const float* __restrict__ vb0,
    const float* __restrict__ vW1, const float* __restrict__ vb1,
    const float* __restrict__ vW2, const float* __restrict__ vb2,
    float* __restrict__ out) {
    extern __shared__ float sm[];
    float* sXh  = sm;                    // 8 x 20 x 7
    float* sXo  = sXh + BT * 140;        // 8 x 10 x 7
    float* sXr  = sXo + BT * 70;         // 8 x 6
    float* sBuf = sXr + BT * 6;          // 2 x 128 x 18 h1 k-slices
    float* sE   = sBuf + 2 * 128 * BUFS; // 128 x 66 (half-N e tile; later HR + sVEC)
    float* sE2  = sE + 128 * SES;        // 8 x 30 x 32 (later value scratch)
    float* sESS = sE2 + BT * 960;        // 8 x 384 [er|sh|so]
    float* sVEC = sE + 1024;             // alias (after GEMM phase)

    const int tid = threadIdx.x;
    const int b0 = blockIdx.x * BT;
    const int lane = tid & 31, warp = tid >> 5;

    for (int i = tid; i < BT * 140; i += NT) {
        int b = i / 140, r = i % 140, nl = r / 7, f = r % 7;
        sXh[i] = state[(b0 + b) * 390 + nl * 13 + 6 + f];
    }
    for (int i = tid; i < BT * 70; i += NT) {
        int b = i / 70, r = i % 70, nl = r / 7, f = r % 7;
        sXo[i] = state[(b0 + b) * 390 + (20 + nl) * 13 + 6 + f];
    }
    if (tid < BT * 6) {
        int b = tid / 6, f = tid % 6;
        sXr[tid] = state[(b0 + b) * 390 + f];
    }
    for (int i = tid; i < BT * 384; i += NT) sESS[i] = 0.f;
    __syncthreads();

    // producer thread mapping (fixed across passes)
    const int c2 = tid & 7;              // cols {c2, c2+8} of each k-slice
    const int rowgrp = tid >> 3;         // 4 local rows: rowgrp*4..+3

    // consumer (mma) mapping
    const int t4 = lane & 3;
    const int rql = lane >> 2;           // 0..7

    for (int pass = 0; pass < 4; ++pass) {
        const int g = pass >> 1, nh = pass & 1;

        // --- warp strip config ---
        int tI;
        if (g == 0) tI = 0;
        else tI = (warp < 2) ? 0 : (warp < 7) ? 1 : 2;
        const float* b1g = (tI == 0) ? whb1 : (tI == 1) ? wob1 : wrb1;

        // --- producer config: type + x regs (4 rows x 7) ---
        int ptype;
        {
            int absr = g * 128 + rowgrp * 4;
            ptype = (absr < 160) ? 0 : (absr < 240) ? 1 : 2;
        }
        const float* W0g = (ptype == 0) ? whW0 : (ptype == 1) ? woW0 : wrW0;
        const float* b0g = (ptype == 0) ? whb0 : (ptype == 1) ? wob0 : wrb0;
        float xr[4][7];
#pragma unroll
        for (int i = 0; i < 4; ++i) {
            int absr = g * 128 + rowgrp * 4 + i;
            const float* src;
            int nf;
            if (absr < 160)      { int b = absr / 20; src = sXh + b * 140 + (absr % 20) * 7; nf = 7; }
            else if (absr < 240) { int idx = absr - 160; int b = idx / 10; src = sXo + b * 70 + (idx % 10) * 7; nf = 7; }
            else                 { int b = absr - 240; src = (b < 8) ? (sXr + b * 6) : nullptr; nf = 6; }
#pragma unroll
            for (int f = 0; f < 7; ++f)
                xr[i][f] = (src && f < nf) ? src[f] : 0.f;
        }

        float acc[8][4];
#pragma unroll
        for (int n = 0; n < 8; ++n)
#pragma unroll
            for (int j = 0; j < 4; ++j) acc[n][j] = 0.f;

        // --- produce k-slice 0 ---
        {
            float* buf = sBuf;
#pragma unroll
            for (int cc = 0; cc < 2; ++cc) {
                const int c = c2 + cc * 8;
                float w[7];
#pragma unroll
                for (int f = 0; f < 6; ++f) w[f] = W0g[f * 256 + c];
                w[6] = (ptype == 2) ? 0.f : W0g[6 * 256 + c];
                const float bias = b0g[c];
#pragma unroll
                for (int i = 0; i < 4; ++i) {
                    float v = bias;
#pragma unroll
                    for (int f = 0; f < 7; ++f) v += xr[i][f] * w[f];
                    buf[(rowgrp * 4 + i) * BUFS + c] = fmaxf(v, 0.f);
                }
            }
        }
        __syncthreads();

        const int r0 = warp * 16 + rql;
        for (int ks = 0; ks < 16; ++ks) {
            if (ks < 15) {   // produce slice ks+1
                float* buf = sBuf + ((ks + 1) & 1) * (128 * BUFS);
                const int k0 = (ks + 1) * 16;
#pragma unroll
                for (int cc = 0; cc < 2; ++cc) {
                    const int c = c2 + cc * 8;
                    float w[7];
#pragma unroll
                    for (int f = 0; f < 6; ++f) w[f] = W0g[f * 256 + k0 + c];
                    w[6] = (ptype == 2) ? 0.f : W0g[6 * 256 + k0 + c];
                    const float bias = b0g[k0 + c];
#pragma unroll
                    for (int i = 0; i < 4; ++i) {
                        float v = bias;
#pragma unroll
                        for (int f = 0; f < 7; ++f) v += xr[i][f] * w[f];
                        buf[(rowgrp * 4 + i) * BUFS + c] = fmaxf(v, 0.f);
                    }
                }
            }
            // consume slice ks
            {
                const float* buf = sBuf + (ks & 1) * (128 * BUFS);
                float2 p00 = *reinterpret_cast<const float2*>(&buf[r0 * BUFS + 2 * t4]);
                float2 p01 = *reinterpret_cast<const float2*>(&buf[r0 * BUFS + 2 * t4 + 8]);
                float2 p10 = *reinterpret_cast<const float2*>(&buf[(r0 + 8) * BUFS + 2 * t4]);
                float2 p11 = *reinterpret_cast<const float2*>(&buf[(r0 + 8) * BUFS + 2 * t4 + 8]);
                uint32_t ah0, al0, ah1, al1, ah2, al2, ah3, al3;
                split_pair(p00.x, p00.y, ah0, al0);
                split_pair(p10.x, p10.y, ah1, al1);
                split_pair(p01.x, p01.y, ah2, al2);
                split_pair(p11.x, p11.y, ah3, al3);

                const uint4* Bp = g_Bfrag + (((tI * 16 + ks) * 16 + nh * 8) * 32) + lane;
#pragma unroll
                for (int nt = 0; nt < 8; ++nt) {
                    uint4 v = Bp[nt * 32];
                    mma_bf16(acc[nt][0], acc[nt][1], acc[nt][2], acc[nt][3],
                             ah0, ah1, ah2, ah3, v.x, v.y);
                    mma_bf16(acc[nt][0], acc[nt][1], acc[nt][2], acc[nt][3],
                             al0, al1, al2, al3, v.x, v.y);
                    mma_bf16(acc[nt][0], acc[nt][1], acc[nt][2], acc[nt][3],
                             ah0, ah1, ah2, ah3, v.z, v.w);
                }
            }
            __syncthreads();
        }

        // bias + relu -> sE (half-N tile, local cols 0..63)
        {
#pragma unroll
            for (int nt = 0; nt < 8; ++nt) {
                const int c = nt * 8 + 2 * t4;
                const float be = b1g[nh * 64 + c], bo = b1g[nh * 64 + c + 1];
                float2 e0, e1;
                e0.x = fmaxf(acc[nt][0] + be, 0.f);
                e0.y = fmaxf(acc[nt][1] + bo, 0.f);
                e1.x = fmaxf(acc[nt][2] + be, 0.f);
                e1.y = fmaxf(acc[nt][3] + bo, 0.f);
                *reinterpret_cast<float2*>(&sE[r0 * SES + c]) = e0;
                *reinterpret_cast<float2*>(&sE[(r0 + 8) * SES + c]) = e1;
            }
        }
        __syncthreads();

        // per-batch sums -> sESS (+=), segment tables per group
        {
            const int c = tid & 63, slot = tid >> 6;
            const int nsegs = (g == 0) ? 7 : 10;
            for (int i = slot; i < nsegs; i += 4) {
                int s, e, b, off;
                if (g == 0) { s = 20 * i; e = min(128, s + 20); b = i; off = 128; }
                else if (i == 0) { s = 0; e = 12; b = 6; off = 128; }
                else if (i == 1) { s = 12; e = 32; b = 7; off = 128; }
                else { int j = i - 2; s = 32 + 10 * j; e = s + 10; b = j; off = 256; }
                float sum = 0.f;
                for (int r = s; r < e; ++r) sum += sE[r * SES + c];
                sESS[b * 384 + off + nh * 64 + c] += sum;
            }
        }
        // er copy (group 1 only)
        if (g == 1) {
            for (int i = tid; i < 512; i += NT) {
                int b = i >> 6, c = i & 63;
                sESS[b * 384 + nh * 64 + c] = sE[(112 + b) * SES + c];
            }
        }
        // e2 = e @ M (accumulate over halves)
        {
            const int cq = tid & 7, rs = tid >> 3;
            const int nrowmax = (g == 0) ? 128 : 112;
#pragma unroll
            for (int j = 0; j < 4; ++j) {
                const int r = rs + j * 32;
                if (r >= nrowmax) break;
                const int absr = g * 128 + r;
                int b, node;
                const float* Mg;
                if (absr < 160) { b = absr / 20; node = absr % 20; Mg = g_Mh; }
                else { int idx = absr - 160; b = idx / 10; node = 20 + idx % 10; Mg = g_Mo; }
                const float4* M4 = reinterpret_cast<const float4*>(Mg) + cq;
                const float* Er = &sE[r * SES];
                float4 a4 = make_float4(0.f, 0.f, 0.f, 0.f);
#pragma unroll 4
                for (int k = 0; k < 64; ++k) {
                    const float ev = Er[k];
                    const float4 w4 = M4[(nh * 64 + k) * 8];
                    a4.x += ev * w4.x; a4.y += ev * w4.y;
                    a4.z += ev * w4.z; a4.w += ev * w4.w;
                }
                float4* dst = reinterpret_cast<float4*>(&sE2[b * 960 + node * 32]) + cq;
                if (nh == 0) *dst = a4;
                else {
                    float4 p = *dst;
                    p.x += a4.x; p.y += a4.y; p.z += a4.z; p.w += a4.w;
                    *dst = p;
                }
            }
        }
        __syncthreads();
    }

    // ---- conv1 commons + per-node relu sums -> sVEC ----
    {
        const int b = tid >> 5, c0 = tid & 31;
        float a0 = g_Gb[c0], a1 = g_Gb[c0 + 32], a2 = g_Gb[c0 + 64];
        const float* in = &sESS[b * 384];
#pragma unroll 4
        for (int k = 0; k < 384; ++k) {
            const float av = in[k];
            a0 += av * g_G[k * 96 + c0];
            a1 += av * g_G[k * 96 + c0 + 32];
            a2 += av * g_G[k * 96 + c0 + 64];
        }
        float sh2 = 0.f, so2 = 0.f;
        const float* e2b = &sE2[b * 960];
#pragma unroll
        for (int n = 0; n < 20; ++n) sh2 += fmaxf(a0 + e2b[n * 32 + c0], 0.f);
#pragma unroll
        for (int n = 0; n < 10; ++n) so2 += fmaxf(a1 + e2b[(20 + n) * 32 + c0], 0.f);
        sVEC[b * 96 + c0]      = sh2;
        sVEC[b * 96 + 32 + c0] = so2;
        sVEC[b * 96 + 64 + c0] = fmaxf(a2, 0.f);
    }
    __syncthreads();

    // ---- hr = relu([sh2|so2|r1] @ G2 + b2) -> sE[0..1023] ----
    {
        const int b = tid >> 5, cg = tid & 31;
        float a[4];
#pragma unroll
        for (int j = 0; j < 4; ++j) a[j] = g_b2[cg + 32 * j];
        const float* in = &sVEC[b * 96];
#pragma unroll 4
        for (int k = 0; k < 96; ++k) {
            const float av = in[k];
#pragma unroll
            for (int j = 0; j < 4; ++j) a[j] += av * g_G2[k * 128 + cg + 32 * j];
        }
#pragma unroll
        for (int j = 0; j < 4; ++j)
            sE[b * 128 + cg + 32 * j] = fmaxf(a[j], 0.f);
    }
    __syncthreads();

    // ---- value MLP ----
    {
        const int col = tid;
        float a[8];
        const float bias = vb0[col];
#pragma unroll
        for (int i = 0; i < 8; ++i) a[i] = bias;
#pragma unroll 4
        for (int k = 0; k < 128; ++k) {
            const float w = vW0[k * 256 + col];
#pragma unroll
            for (int i = 0; i < 8; ++i) a[i] += sE[i * 128 + k] * w;
        }
#pragma unroll
        for (int i = 0; i < 8; ++i)
            sE2[i * 256 + col] = fmaxf(a[i], 0.f);
    }
    __syncthreads();
    {
        const int col = tid & 127, gq = tid >> 7;
        float a[4];
        const float bias = vb1[col];
#pragma unroll
        for (int i = 0; i < 4; ++i) a[i] = bias;
#pragma unroll 4
        for (int k = 0; k < 256; ++k) {
            const float w = vW1[k * 128 + col];
#pragma unroll
            for (int i = 0; i < 4; ++i) a[i] += sE2[(gq * 4 + i) * 256 + k] * w;
        }
#pragma unroll
        for (int i = 0; i < 4; ++i)
            sE2[2048 + (gq * 4 + i) * 128 + col] = fmaxf(a[i], 0.f);
    }
    __syncthreads();
    {
        const int b = warp, l = lane;
        float s = 0.f;
#pragma unroll
        for (int k = l; k < 128; k += 32) s += sE2[2048 + b * 128 + k] * vW2[k];
#pragma unroll
        for (int off = 16; off > 0; off >>= 1)
            s += __shfl_down_sync(0xffffffffu, s, off);
        if (l == 0) out[b0 + b] = s + vb2[0];
    }
}

// ============================================================
extern "C" void kernel_launch(void* const* d_in, const int* in_sizes, int n_in,
                              void* d_out, int out_size) {
    const float* state   = (const float*)d_in[0];
    const float* wrW0    = (const float*)d_in[2];
    const float* wrb0    = (const float*)d_in[3];
    const float* wrW1    = (const float*)d_in[4];
    const float* wrb1    = (const float*)d_in[5];
    const float* whW0    = (const float*)d_in[6];
    const float* whb0    = (const float*)d_in[7];
    const float* whW1    = (const float*)d_in[8];
    const float* whb1    = (const float*)d_in[9];
    const float* woW0    = (const float*)d_in[10];
    const float* wob0    = (const float*)d_in[11];
    const float* woW1    = (const float*)d_in[12];
    const float* wob1    = (const float*)d_in[13];
    const float* c1_relW = (const float*)d_in[14];
    const float* c1_relb = (const float*)d_in[15];
    const float* c1_rootW= (const float*)d_in[16];
    const float* c2_relW = (const float*)d_in[17];
    const float* c2_relb = (const float*)d_in[18];
    const float* c2_rootW= (const float*)d_in[19];
    const float* vW0     = (const float*)d_in[20];
    const float* vb0     = (const float*)d_in[21];
    const float* vW1     = (const float*)d_in[22];
    const float* vb1     = (const float*)d_in[23];
    const float* vW2     = (const float*)d_in[24];
    const float* vb2     = (const float*)d_in[25];
    float* out = (float*)d_out;

    cudaFuncSetAttribute(main_kernel, cudaFuncAttributeMaxDynamicSharedMemorySize,
                         MAIN_SMEM_FLOATS * 4);

    prep_kernel<<<96, 256>>>(c1_relW, c1_relb, c1_rootW, c2_relW, c2_relb, c2_rootW,
                             whW1, woW1, wrW1);

    main_kernel<<<BATCH / BT, NT, MAIN_SMEM_FLOATS * 4>>>(
        state, wrW0, wrb0, wrb1, whW0, whb0, whb1,
        woW0, wob0, wob1,
        vW0, vb0, vW1, vb1, vW2, vb2, out);
}